// round 3
// baseline (speedup 1.0000x reference)
#include <cuda_runtime.h>
#include <cstddef>
#include <cstdint>

typedef unsigned long long ull;

// Problem constants
#define A_ 4
#define B_ 8
#define S_ 2048
#define D_ 256
#define N_ 32      // A_*B_
#define H_ 256
#define G_ 1024    // 4*H_

// -------- scratch (device globals; allocation-free per harness rules) --------
__device__ float g_f[(size_t)N_ * S_ * D_];
__device__ float g_xw0[(size_t)N_ * S_ * G_];
__device__ float g_xw1[(size_t)N_ * S_ * G_];
__device__ float g_hseq0[(size_t)N_ * S_ * H_];
__device__ float g_hseq1[(size_t)N_ * S_ * H_];
__device__ float g_hbuf[(size_t)N_ * S_ * D_];
__device__ float g_zp[B_ * D_];

__device__ __forceinline__ float fsig(float x) { return 1.f / (1.f + __expf(-x)); }
__device__ __forceinline__ float ftanh(float x) {
    float t = __expf(-2.f * fabsf(x));
    float r = (1.f - t) / (1.f + t);
    return copysignf(r, x);
}

// f32x2 packed-math helpers (sm_103a FFMA2 — only reachable via PTX)
#define FMA2(acc, a, b) asm("fma.rn.f32x2 %0, %1, %2, %0;" : "+l"(acc) : "l"(a), "l"(b))
#define PACKD(out, v)                                                        \
    do { unsigned _u = __float_as_uint(v);                                   \
         asm("mov.b64 %0, {%1, %1};" : "=l"(out) : "r"(_u)); } while (0)
#define UNPK(lo, hi, v)                                                      \
    do { unsigned _a, _b;                                                    \
         asm("mov.b64 {%0, %1}, %2;" : "=r"(_a), "=r"(_b) : "l"(v));         \
         lo = __uint_as_float(_a); hi = __uint_as_float(_b); } while (0)

__device__ __forceinline__ unsigned ctarank() {
    unsigned r; asm("mov.u32 %0, %%cluster_ctarank;" : "=r"(r)); return r;
}
__device__ __forceinline__ unsigned smem_u32(const void* p) {
    return (unsigned)__cvta_generic_to_shared(p);
}

// ------------------------- z / zp (tiny matvec) ------------------------------
__global__ void k_zzp(const float* __restrict__ hin, const float* __restrict__ W4,
                      const float* __restrict__ b4) {
    __shared__ float zs[D_];
    int b = blockIdx.x;       // 0..7
    int e = threadIdx.x;      // 0..255
    float s = 0.f;
#pragma unroll
    for (int a = 0; a < A_; ++a)
        s += hin[(((size_t)(a * B_ + b)) * S_ + (S_ - 1)) * D_ + e];
    zs[e] = s * (1.f / 3.f);  // sum over agents / (A-1)
    __syncthreads();
    float acc = b4[e];
#pragma unroll 8
    for (int d = 0; d < D_; ++d) acc += zs[d] * W4[d * D_ + e];
    g_zp[b * D_ + e] = acc;
}

// ------------------------------ SGEMM (f32x2) --------------------------------
// C[M x NDIM] = op(A)[M x KDIM] @ Bw[KDIM x NDIM] + bias (+ optional zp + tanh)
// AMODE 0: A0[m][k]
// AMODE 1: A0[(n, S-1-s)][k]                (time-reversed rows; m = n*S+s)
// AMODE 2: k<256 -> A0[(n,s)][k] ; k>=256 -> A1[(n,S-1-s)][k-256]  (concat)
// EPI 0: +bias   EPI 1: tanh(v + bias + g_zp[b])
template <int AMODE, int EPI, int KDIM, int NDIM>
__global__ void __launch_bounds__(256, 2)
k_gemm(const float* __restrict__ A0, const float* __restrict__ A1,
       const float* __restrict__ Bw, const float* __restrict__ bias,
       float* __restrict__ C) {
    __shared__ float As[8][128];
    __shared__ float Bs[8][128];
    const int tid = threadIdx.x;
    const int m0 = blockIdx.y * 128;
    const int n0 = blockIdx.x * 128;
    const int aRow = tid >> 1;
    const int aCol = (tid & 1) * 4;
    const int bRow = tid >> 5;
    const int bCol = (tid & 31) * 4;
    const int tr = (tid >> 4) * 8;
    const int tc = (tid & 15) * 8;

    const int m = m0 + aRow;
    const float* aP0;
    const float* aP1 = nullptr;
    if (AMODE == 0) {
        aP0 = A0 + (size_t)m * KDIM;
    } else if (AMODE == 1) {
        int n = m >> 11, s = m & 2047;
        aP0 = A0 + ((size_t)(n << 11) + (2047 - s)) * KDIM;
    } else {
        int n = m >> 11, s = m & 2047;
        aP0 = A0 + (size_t)m * 256;
        aP1 = A1 + ((size_t)(n << 11) + (2047 - s)) * 256;
    }
    const float* bP = Bw + (size_t)bRow * NDIM + n0 + bCol;

    ull acc2[8][4];
#pragma unroll
    for (int i = 0; i < 8; ++i)
#pragma unroll
        for (int j = 0; j < 4; ++j) acc2[i][j] = 0ull;

    for (int k0 = 0; k0 < KDIM; k0 += 8) {
        float4 av;
        if (AMODE < 2) {
            av = *(const float4*)(aP0 + k0 + aCol);
        } else {
            int kk = k0 + aCol;
            av = (kk < 256) ? *(const float4*)(aP0 + kk)
                            : *(const float4*)(aP1 + (kk - 256));
        }
        float4 bv = *(const float4*)(bP + (size_t)k0 * NDIM);
        As[aCol + 0][aRow] = av.x;
        As[aCol + 1][aRow] = av.y;
        As[aCol + 2][aRow] = av.z;
        As[aCol + 3][aRow] = av.w;
        *(float4*)&Bs[bRow][bCol] = bv;
        __syncthreads();
#pragma unroll
        for (int kk = 0; kk < 8; ++kk) {
            float ra[8];
            *(float4*)(ra)     = *(const float4*)&As[kk][tr];
            *(float4*)(ra + 4) = *(const float4*)&As[kk][tr + 4];
            ulonglong2 rb0 = *(const ulonglong2*)&Bs[kk][tc];
            ulonglong2 rb1 = *(const ulonglong2*)&Bs[kk][tc + 4];
#pragma unroll
            for (int i = 0; i < 8; ++i) {
                ull ap; PACKD(ap, ra[i]);
                FMA2(acc2[i][0], ap, rb0.x);
                FMA2(acc2[i][1], ap, rb0.y);
                FMA2(acc2[i][2], ap, rb1.x);
                FMA2(acc2[i][3], ap, rb1.y);
            }
        }
        __syncthreads();
    }

#pragma unroll
    for (int i = 0; i < 8; ++i) {
        int mm = m0 + tr + i;
        float* crow = C + (size_t)mm * NDIM + n0 + tc;
        int bi = 0;
        if (EPI == 1) bi = (mm >> 11) & 7;   // n = m>>11 ; b = n & 7
        float cv[8];
#pragma unroll
        for (int j2 = 0; j2 < 4; ++j2) UNPK(cv[2 * j2], cv[2 * j2 + 1], acc2[i][j2]);
#pragma unroll
        for (int j4 = 0; j4 < 8; j4 += 4) {
            int col = n0 + tc + j4;
            float4 v = make_float4(cv[j4], cv[j4 + 1], cv[j4 + 2], cv[j4 + 3]);
            v.x += bias[col]; v.y += bias[col + 1]; v.z += bias[col + 2]; v.w += bias[col + 3];
            if (EPI == 1) {
                const float* zr = &g_zp[bi * D_];
                v.x = ftanh(v.x + zr[col]);     v.y = ftanh(v.y + zr[col + 1]);
                v.z = ftanh(v.z + zr[col + 2]); v.w = ftanh(v.w + zr[col + 3]);
            }
            *(float4*)(crow + j4) = v;
        }
    }
}

// --------------------------- cluster LSTM scan -------------------------------
// 16 clusters of 8 CTAs. Cluster c: dir = c>>3, seq group sg = c&7 (4 seqs).
// CTA rank r owns hidden units j in [r*32, r*32+32) -> gate cols {j,256+j,512+j,768+j}.
// Wh slice [256 x 128] lives in smem for the whole scan. Per step:
//   all 256 threads: partial GEMM (K split in halves, f32x2 packed gate-pairs)
//   -> smem reduction -> 128 threads do activations + write h to all 8 CTAs'
//   smem via mapa/st.shared::cluster -> barrier.cluster. No L2 traffic for h.
#define SCAN_SMEM_FLOATS (32768 + 2048 + 1024)
__global__ void __launch_bounds__(256, 1) __cluster_dims__(8, 1, 1)
k_scan2(const float* __restrict__ Whf, const float* __restrict__ Whb) {
    extern __shared__ float sm[];
    float* Wsl = sm;                  // [256][128]: Wsl[k][jj*4+g] = Wh[k][g*256+jbase+jj]
    float* hp  = sm + 32768;          // [2][4][256] h double-buffer (full h per seq)
    float* red = sm + 32768 + 2048;   // [256] x float4 partials

    const int tid = threadIdx.x;
    const unsigned rank = ctarank();
    const int cidx = blockIdx.x >> 3;
    const int dir  = cidx >> 3;
    const int sg   = cidx & 7;
    const float* Wh   = dir ? Whb : Whf;
    const float* xw   = dir ? g_xw1 : g_xw0;
    float*       hseq = dir ? g_hseq1 : g_hseq0;
    const int jbase = (int)rank * 32;

    // one-time Wh slice load (L2-shared across the 8 clusters per direction)
    for (int idx = tid; idx < 32768; idx += 256) {
        int k = idx >> 7, c = idx & 127, jj = c >> 2, g = c & 3;
        Wsl[idx] = Wh[(size_t)k * G_ + g * 256 + jbase + jj];
    }
    __syncthreads();

    // GEMM roles (all 256 threads)
    const int kh = tid >> 7;            // K half
    const int cg = (tid >> 2) & 31;     // hidden unit within slice
    const int nn = tid & 3;             // local sequence
    // epilogue roles (tid < 128)
    const int jj2 = tid & 31;
    const int nn2 = tid >> 5;
    const int nG  = sg * 4 + nn2;       // global sequence
    float creg = 0.f;

    const float4* Wv = (const float4*)Wsl;

    for (int t = 0; t < S_; ++t) {
        // prefetch input projections (DRAM; overlaps with the GEMM)
        float xi = 0.f, xf = 0.f, xg = 0.f, xo = 0.f;
        if (tid < 128) {
            const float* xp = xw + ((size_t)nG * S_ + t) * G_ + jbase + jj2;
            xi = __ldcg(xp);
            xf = __ldcg(xp + 256);
            xg = __ldcg(xp + 512);
            xo = __ldcg(xp + 768);
        }

        ull aif = 0ull, ago = 0ull;
        if (t > 0) {
            const float* hpR = hp + (t & 1) * 1024 + nn * 256;
            const int kb0 = kh * 32;
#pragma unroll 4
            for (int kb = 0; kb < 32; ++kb) {
                const int k = (kb0 + kb) * 4;
                float4 h4 = *(const float4*)(hpR + k);
                ulonglong2 w0 = *(const ulonglong2*)&Wv[(k + 0) * 32 + cg];
                ulonglong2 w1 = *(const ulonglong2*)&Wv[(k + 1) * 32 + cg];
                ulonglong2 w2 = *(const ulonglong2*)&Wv[(k + 2) * 32 + cg];
                ulonglong2 w3 = *(const ulonglong2*)&Wv[(k + 3) * 32 + cg];
                ull h0, h1, h2, h3;
                PACKD(h0, h4.x); PACKD(h1, h4.y); PACKD(h2, h4.z); PACKD(h3, h4.w);
                FMA2(aif, w0.x, h0); FMA2(ago, w0.y, h0);
                FMA2(aif, w1.x, h1); FMA2(ago, w1.y, h1);
                FMA2(aif, w2.x, h2); FMA2(ago, w2.y, h2);
                FMA2(aif, w3.x, h3); FMA2(ago, w3.y, h3);
            }
        }

        {   // K-half partials -> smem
            ulonglong2 st; st.x = aif; st.y = ago;
            ((ulonglong2*)red)[tid] = st;
        }
        __syncthreads();

        if (tid < 128) {
            const float4 p = ((const float4*)red)[jj2 * 4 + nn2];
            const float4 q = ((const float4*)red)[128 + jj2 * 4 + nn2];
            float gi = p.x + q.x + xi;
            float gf = p.y + q.y + xf;
            float gg = p.z + q.z + xg;
            float go = p.w + q.w + xo;
            float ii = fsig(gi), ff = fsig(gf);
            float g2 = ftanh(gg), oo = fsig(go);
            creg = ff * creg + ii * g2;
            float hv = oo * ftanh(creg);
            __stcg(&hseq[((size_t)nG * S_ + t) * H_ + jbase + jj2], hv);
            if (t < S_ - 1) {
                // broadcast new h to every CTA in the cluster (incl. self)
                unsigned a = smem_u32(&hp[((t + 1) & 1) * 1024 + nn2 * 256 + jbase + jj2]);
#pragma unroll
                for (unsigned r = 0; r < 8; ++r) {
                    asm volatile(
                        "{ .reg .u32 ra;\n\t"
                        "  mapa.shared::cluster.u32 ra, %0, %1;\n\t"
                        "  st.shared::cluster.f32 [ra], %2; }"
                        :: "r"(a), "r"(r), "f"(hv));
                }
            }
        }
        if (t < S_ - 1) {
            asm volatile("barrier.cluster.arrive.aligned;" ::: "memory");
            asm volatile("barrier.cluster.wait.aligned;" ::: "memory");
        }
    }
    // drain before any CTA of the cluster exits
    asm volatile("barrier.cluster.arrive.aligned;" ::: "memory");
    asm volatile("barrier.cluster.wait.aligned;" ::: "memory");
}

// ------------------------------ launcher -------------------------------------
extern "C" void kernel_launch(void* const* d_in, const int* in_sizes, int n_in,
                              void* d_out, int out_size) {
    const float* x   = (const float*)d_in[0];
    const float* W3  = (const float*)d_in[1];
    const float* b3  = (const float*)d_in[2];
    const float* W4  = (const float*)d_in[3];
    const float* b4  = (const float*)d_in[4];
    const float* Wxf = (const float*)d_in[5];
    const float* Whf = (const float*)d_in[6];
    const float* bf  = (const float*)d_in[7];
    const float* Wxb = (const float*)d_in[8];
    const float* Whb = (const float*)d_in[9];
    const float* bb  = (const float*)d_in[10];
    const float* Wd  = (const float*)d_in[11];
    const float* bd  = (const float*)d_in[12];
    float* out = (float*)d_out;

    float *pf, *pxw0, *pxw1, *ph0, *ph1, *phbuf;
    cudaGetSymbolAddress((void**)&pf,    g_f);
    cudaGetSymbolAddress((void**)&pxw0,  g_xw0);
    cudaGetSymbolAddress((void**)&pxw1,  g_xw1);
    cudaGetSymbolAddress((void**)&ph0,   g_hseq0);
    cudaGetSymbolAddress((void**)&ph1,   g_hseq1);
    cudaGetSymbolAddress((void**)&phbuf, g_hbuf);

    cudaFuncSetAttribute(k_scan2, cudaFuncAttributeMaxDynamicSharedMemorySize,
                         SCAN_SMEM_FLOATS * 4);

    for (int it = 0; it < 2; ++it) {
        const float* hin = (it == 0) ? x : phbuf;
        float* hout = (it == 1) ? out : phbuf;

        // zp = (sum_a h[:, :, -1, :]/3) @ W4 + b4
        k_zzp<<<B_, D_>>>(hin, W4, b4);
        // f = tanh(h @ W3 + b3 + zp[b])
        k_gemm<0, 1, 256, 256><<<dim3(2, 512), 256>>>(hin, nullptr, W3, b3, pf);
        // gate input projections (fwd + time-reversed bwd)
        k_gemm<0, 0, 256, 1024><<<dim3(8, 512), 256>>>(pf, nullptr, Wxf, bf, pxw0);
        k_gemm<1, 0, 256, 1024><<<dim3(8, 512), 256>>>(pf, nullptr, Wxb, bb, pxw1);
        // cluster-local bidirectional LSTM scan
        k_scan2<<<128, 256, SCAN_SMEM_FLOATS * 4>>>(Whf, Whb);
        // h = concat(hf, hb_rev) @ Wd + bd
        k_gemm<2, 0, 512, 256><<<dim3(2, 512), 256>>>(ph0, ph1, Wd, bd, hout);
    }
}

// round 4
// speedup vs baseline: 1.0725x; 1.0725x over previous
#include <cuda_runtime.h>
#include <cstddef>
#include <cstdint>

typedef unsigned long long ull;

// Problem constants
#define A_ 4
#define B_ 8
#define S_ 2048
#define D_ 256
#define N_ 32      // A_*B_
#define H_ 256
#define G_ 1024    // 4*H_
#define P_ 64      // scan CTAs per direction
#define JH 4       // hidden units per scan CTA
#define WPAD 20

// -------- scratch (device globals; allocation-free per harness rules) --------
__device__ float g_f[(size_t)N_ * S_ * D_];
__device__ float g_xw0[(size_t)N_ * S_ * G_];
__device__ float g_xw1[(size_t)N_ * S_ * G_];
__device__ float g_hseq0[(size_t)S_ * N_ * H_];   // [t][n][j] layout
__device__ float g_hseq1[(size_t)S_ * N_ * H_];   // [t][n][j] layout
__device__ float g_hbuf[(size_t)N_ * S_ * D_];
__device__ float g_hstate[2][2][H_ * N_];         // [dir][buf][j*32 + n]
__device__ float g_zp[B_ * D_];
__device__ int   g_flags[2][P_];                  // [dir][cta] step counters

__device__ __forceinline__ float fsig(float x) { return 1.f / (1.f + __expf(-x)); }
__device__ __forceinline__ float ftanh(float x) {
    float t = __expf(-2.f * fabsf(x));
    float r = (1.f - t) / (1.f + t);
    return copysignf(r, x);
}

// f32x2 packed FFMA (sm_103a; only reachable via PTX)
#define FMA2(acc, a, b) asm("fma.rn.f32x2 %0, %1, %2, %0;" : "+l"(acc) : "l"(a), "l"(b))
#define PACKD(out, v)                                                        \
    do { unsigned _u = __float_as_uint(v);                                   \
         asm("mov.b64 %0, {%1, %1};" : "=l"(out) : "r"(_u)); } while (0)

__device__ __forceinline__ int ld_acq(const int* p) {
    int v; asm volatile("ld.acquire.gpu.global.b32 %0, [%1];" : "=r"(v) : "l"(p)); return v;
}
__device__ __forceinline__ void st_rel(int* p, int v) {
    asm volatile("st.release.gpu.global.b32 [%0], %1;" :: "l"(p), "r"(v) : "memory");
}

// ------------------------------- init ---------------------------------------
__global__ void k_init() {
    if (threadIdx.x < 2 * P_) ((int*)g_flags)[threadIdx.x] = 0;
}

// ------------------------- z / zp (tiny matvec) ------------------------------
__global__ void k_zzp(const float* __restrict__ hin, const float* __restrict__ W4,
                      const float* __restrict__ b4) {
    __shared__ float zs[D_];
    int b = blockIdx.x;
    int e = threadIdx.x;
    float s = 0.f;
#pragma unroll
    for (int a = 0; a < A_; ++a)
        s += hin[(((size_t)(a * B_ + b)) * S_ + (S_ - 1)) * D_ + e];
    zs[e] = s * (1.f / 3.f);
    __syncthreads();
    float acc = b4[e];
#pragma unroll 8
    for (int d = 0; d < D_; ++d) acc += zs[d] * W4[d * D_ + e];
    g_zp[b * D_ + e] = acc;
}

// ------------------------------ SGEMM ----------------------------------------
// C[M x NDIM] = op(A)[M x KDIM] @ Bw[KDIM x NDIM] + bias (+ optional zp + tanh)
// AMODE 0: A0[m][k]
// AMODE 1: A0[(n, S-1-s)][k]          (time-reversed rows; m = n*S+s)
// AMODE 3: concat from [t][n][j] layout:
//          k<256 -> A0[(s*32+n)][k] ; k>=256 -> A1[((S-1-s)*32+n)][k-256]
// EPI 0: +bias   EPI 1: tanh(v + bias + g_zp[b])
template <int AMODE, int EPI, int KDIM, int NDIM>
__global__ void __launch_bounds__(256, 2)
k_gemm(const float* __restrict__ A0, const float* __restrict__ A1,
       const float* __restrict__ Bw, const float* __restrict__ bias,
       float* __restrict__ C) {
    __shared__ float As[8][128];
    __shared__ float Bs[8][128];
    const int tid = threadIdx.x;
    const int m0 = blockIdx.y * 128;
    const int n0 = blockIdx.x * 128;
    const int aRow = tid >> 1;
    const int aCol = (tid & 1) * 4;
    const int bRow = tid >> 5;
    const int bCol = (tid & 31) * 4;
    const int tr = (tid >> 4) * 8;
    const int tc = (tid & 15) * 8;

    const int m = m0 + aRow;
    const float* aP0;
    const float* aP1 = nullptr;
    if (AMODE == 0) {
        aP0 = A0 + (size_t)m * KDIM;
    } else if (AMODE == 1) {
        int n = m >> 11, s = m & 2047;
        aP0 = A0 + ((size_t)(n << 11) + (2047 - s)) * KDIM;
    } else {
        int n = m >> 11, s = m & 2047;
        aP0 = A0 + ((size_t)(s * 32) + n) * 256;
        aP1 = A1 + ((size_t)((2047 - s) * 32) + n) * 256;
    }
    const float* bP = Bw + (size_t)bRow * NDIM + n0 + bCol;

    float acc[8][8];
#pragma unroll
    for (int i = 0; i < 8; ++i)
#pragma unroll
        for (int j = 0; j < 8; ++j) acc[i][j] = 0.f;

    for (int k0 = 0; k0 < KDIM; k0 += 8) {
        float4 av;
        if (AMODE != 3) {
            av = *(const float4*)(aP0 + k0 + aCol);
        } else {
            int kk = k0 + aCol;
            av = (kk < 256) ? *(const float4*)(aP0 + kk)
                            : *(const float4*)(aP1 + (kk - 256));
        }
        float4 bv = *(const float4*)(bP + (size_t)k0 * NDIM);
        As[aCol + 0][aRow] = av.x;
        As[aCol + 1][aRow] = av.y;
        As[aCol + 2][aRow] = av.z;
        As[aCol + 3][aRow] = av.w;
        *(float4*)&Bs[bRow][bCol] = bv;
        __syncthreads();
#pragma unroll
        for (int kk = 0; kk < 8; ++kk) {
            float ra[8], rb[8];
            *(float4*)(ra)     = *(const float4*)&As[kk][tr];
            *(float4*)(ra + 4) = *(const float4*)&As[kk][tr + 4];
            *(float4*)(rb)     = *(const float4*)&Bs[kk][tc];
            *(float4*)(rb + 4) = *(const float4*)&Bs[kk][tc + 4];
#pragma unroll
            for (int i = 0; i < 8; ++i)
#pragma unroll
                for (int j = 0; j < 8; ++j) acc[i][j] += ra[i] * rb[j];
        }
        __syncthreads();
    }

#pragma unroll
    for (int i = 0; i < 8; ++i) {
        int mm = m0 + tr + i;
        float* crow = C + (size_t)mm * NDIM + n0 + tc;
        int bi = 0;
        if (EPI == 1) bi = (mm >> 11) & 7;
#pragma unroll
        for (int j4 = 0; j4 < 8; j4 += 4) {
            int col = n0 + tc + j4;
            float4 v = make_float4(acc[i][j4], acc[i][j4 + 1], acc[i][j4 + 2], acc[i][j4 + 3]);
            v.x += bias[col]; v.y += bias[col + 1]; v.z += bias[col + 2]; v.w += bias[col + 3];
            if (EPI == 1) {
                const float* zr = &g_zp[bi * D_];
                v.x = ftanh(v.x + zr[col]);     v.y = ftanh(v.y + zr[col + 1]);
                v.z = ftanh(v.z + zr[col + 2]); v.w = ftanh(v.w + zr[col + 3]);
            }
            *(float4*)(crow + j4) = v;
        }
    }
}

// --------------------------- persistent LSTM scan ----------------------------
// 128 CTAs: dir = blockIdx>>6, blk = blockIdx&63 -> hidden units [blk*4, blk*4+4).
// Wh slice in smem; gate GEMM uses f32x2 packed FFMA (16 cols = 8 pairs).
// Cross-CTA sync: per-CTA monotonic flag, st.release.gpu / ld.acquire.gpu —
// no atomics, no membar.gl.
__global__ void __launch_bounds__(256, 1)
k_scan(const float* __restrict__ Whf, const float* __restrict__ Whb, int base) {
    __shared__ float Wsl[256 * WPAD];
    __shared__ float red[256 * WPAD];
    const int tid = threadIdx.x;
    const int lane = tid & 31;
    const int w = tid >> 5;
    const int dir = blockIdx.x >> 6;
    const int blk = blockIdx.x & 63;
    const int j0 = blk * JH;
    const float* Wh = dir ? Whb : Whf;
    const float* xw = dir ? g_xw1 : g_xw0;
    float* hseq = dir ? g_hseq1 : g_hseq0;
    int* flags = g_flags[dir];
    int* myflag = &flags[blk];

    // Load Wh slice: Wsl[k][jj*4+gt] = Wh[k][gt*256 + j0 + jj]
    {
        const float* wr = Wh + (size_t)tid * G_ + j0;
        float4 q0 = *(const float4*)(wr);
        float4 q1 = *(const float4*)(wr + 256);
        float4 q2 = *(const float4*)(wr + 512);
        float4 q3 = *(const float4*)(wr + 768);
        float* ws = &Wsl[tid * WPAD];
        ws[0]  = q0.x; ws[1]  = q1.x; ws[2]  = q2.x; ws[3]  = q3.x;
        ws[4]  = q0.y; ws[5]  = q1.y; ws[6]  = q2.y; ws[7]  = q3.y;
        ws[8]  = q0.z; ws[9]  = q1.z; ws[10] = q2.z; ws[11] = q3.z;
        ws[12] = q0.w; ws[13] = q1.w; ws[14] = q2.w; ws[15] = q3.w;
    }
    __syncthreads();

    const int wk0 = w * 32;          // producer: K-chunk base, lane = seq
    const int n2 = tid >> 2;         // epilogue: seq (tid<128)
    const int jj = tid & 3;          //           hidden sub-index
    float creg = 0.f;

    for (int t = 0; t < S_; ++t) {
        // prefetch this step's input projections (overlaps the GEMM)
        float xi = 0.f, xf = 0.f, xg = 0.f, xo = 0.f;
        if (tid < 128) {
            const float* xp = xw + ((size_t)n2 * S_ + t) * G_ + j0 + jj;
            xi = __ldcg(xp);
            xf = __ldcg(xp + 256);
            xg = __ldcg(xp + 512);
            xo = __ldcg(xp + 768);
        }

        ull acc2[8];
#pragma unroll
        for (int c = 0; c < 8; ++c) acc2[c] = 0ull;

        if (t > 0) {
            const float* hb = &g_hstate[dir][(t + 1) & 1][wk0 * N_ + lane];
            float hreg[32];
#pragma unroll
            for (int kk = 0; kk < 32; ++kk) hreg[kk] = __ldcg(hb + kk * N_);
#pragma unroll
            for (int kk = 0; kk < 32; ++kk) {
                const ulonglong2* wp = (const ulonglong2*)&Wsl[(wk0 + kk) * WPAD];
                ulonglong2 wa = wp[0], wb = wp[1];
                ull hp_; PACKD(hp_, hreg[kk]);
                FMA2(acc2[0], wa.x, hp_); FMA2(acc2[1], wa.y, hp_);
                FMA2(acc2[2], wb.x, hp_); FMA2(acc2[3], wb.y, hp_);
                ulonglong2 wc = wp[2], wd = wp[3];
                FMA2(acc2[4], wc.x, hp_); FMA2(acc2[5], wc.y, hp_);
                FMA2(acc2[6], wd.x, hp_); FMA2(acc2[7], wd.y, hp_);
            }
        }

        {   // K-chunk partials -> smem (row = w*32+lane, 16 floats)
            ulonglong2* rr = (ulonglong2*)&red[tid * WPAD];
            rr[0] = make_ulonglong2(acc2[0], acc2[1]);
            rr[1] = make_ulonglong2(acc2[2], acc2[3]);
            rr[2] = make_ulonglong2(acc2[4], acc2[5]);
            rr[3] = make_ulonglong2(acc2[6], acc2[7]);
        }
        __syncthreads();

        if (tid < 128) {
            float4 s = make_float4(0.f, 0.f, 0.f, 0.f);
#pragma unroll
            for (int ww = 0; ww < 8; ++ww) {
                float4 v = *(const float4*)&red[(ww * 32 + n2) * WPAD + jj * 4];
                s.x += v.x; s.y += v.y; s.z += v.z; s.w += v.w;
            }
            float gi = s.x + xi, gf = s.y + xf, gg = s.z + xg, go = s.w + xo;
            float ii = fsig(gi), ff = fsig(gf);
            float g2 = ftanh(gg), oo = fsig(go);
            creg = ff * creg + ii * g2;
            float hv = oo * ftanh(creg);
            __stcg(&g_hstate[dir][t & 1][(j0 + jj) * N_ + n2], hv);
            __stcg(&hseq[((size_t)t * N_ + n2) * H_ + j0 + jj], hv);
        }
        __syncthreads();   // all h stores issued before the release below

        if (t < S_ - 1) {
            const int target = base + t + 1;
            if (tid == 0) st_rel(myflag, target);
            if (tid < P_) {
                while (ld_acq(&flags[tid]) < target) { }
            }
            __syncthreads();
        }
    }
}

// ------------------------------ launcher -------------------------------------
extern "C" void kernel_launch(void* const* d_in, const int* in_sizes, int n_in,
                              void* d_out, int out_size) {
    const float* x   = (const float*)d_in[0];
    const float* W3  = (const float*)d_in[1];
    const float* b3  = (const float*)d_in[2];
    const float* W4  = (const float*)d_in[3];
    const float* b4  = (const float*)d_in[4];
    const float* Wxf = (const float*)d_in[5];
    const float* Whf = (const float*)d_in[6];
    const float* bf  = (const float*)d_in[7];
    const float* Wxb = (const float*)d_in[8];
    const float* Whb = (const float*)d_in[9];
    const float* bb  = (const float*)d_in[10];
    const float* Wd  = (const float*)d_in[11];
    const float* bd  = (const float*)d_in[12];
    float* out = (float*)d_out;

    float *pf, *pxw0, *pxw1, *ph0, *ph1, *phbuf;
    cudaGetSymbolAddress((void**)&pf,    g_f);
    cudaGetSymbolAddress((void**)&pxw0,  g_xw0);
    cudaGetSymbolAddress((void**)&pxw1,  g_xw1);
    cudaGetSymbolAddress((void**)&ph0,   g_hseq0);
    cudaGetSymbolAddress((void**)&ph1,   g_hseq1);
    cudaGetSymbolAddress((void**)&phbuf, g_hbuf);

    k_init<<<1, 128>>>();

    for (int it = 0; it < 2; ++it) {
        const float* hin = (it == 0) ? x : phbuf;
        float* hout = (it == 1) ? out : phbuf;

        // zp = (sum_a h[:, :, -1, :]/3) @ W4 + b4
        k_zzp<<<B_, D_>>>(hin, W4, b4);
        // f = tanh(h @ W3 + b3 + zp[b])
        k_gemm<0, 1, 256, 256><<<dim3(2, 512), 256>>>(hin, nullptr, W3, b3, pf);
        // gate input projections (fwd + time-reversed bwd)
        k_gemm<0, 0, 256, 1024><<<dim3(8, 512), 256>>>(pf, nullptr, Wxf, bf, pxw0);
        k_gemm<1, 0, 256, 1024><<<dim3(8, 512), 256>>>(pf, nullptr, Wxb, bb, pxw1);
        // persistent bidirectional LSTM scan (flag barrier)
        k_scan<<<128, 256>>>(Whf, Whb, it * S_);
        // h = concat(hf, hb_rev) @ Wd + bd   (hseq in [t][n][j] layout)
        k_gemm<3, 0, 512, 256><<<dim3(2, 512), 256>>>(ph0, ph1, Wd, bd, hout);
    }
}

// round 5
// speedup vs baseline: 1.2964x; 1.2087x over previous
#include <cuda_runtime.h>
#include <cstddef>
#include <cstdint>

typedef unsigned long long ull;

// Problem constants
#define A_ 4
#define B_ 8
#define S_ 2048
#define D_ 256
#define N_ 32      // A_*B_
#define H_ 256
#define G_ 1024    // 4*H_
#define P_ 64      // scan CTAs (each handles BOTH directions)
#define JH 4       // hidden units per scan CTA per direction
#define WPAD 20

// -------- scratch (device globals; allocation-free per harness rules) --------
__device__ float g_f[(size_t)N_ * S_ * D_];
__device__ float g_xw0[(size_t)N_ * S_ * G_];
__device__ float g_xw1[(size_t)N_ * S_ * G_];
__device__ float g_hseq0[(size_t)S_ * N_ * H_];   // [t][n][j] layout
__device__ float g_hseq1[(size_t)S_ * N_ * H_];   // [t][n][j] layout
__device__ float g_hbuf[(size_t)N_ * S_ * D_];
__device__ float g_hstate[2][2][H_ * N_];         // [dir][buf][j*32 + n]
__device__ float g_zp[B_ * D_];
__device__ int   g_cnt[2];                        // [dir] monotonic arrival counters

__device__ __forceinline__ float fsig(float x) { return 1.f / (1.f + __expf(-x)); }
__device__ __forceinline__ float ftanh(float x) {
    float t = __expf(-2.f * fabsf(x));
    float r = (1.f - t) / (1.f + t);
    return copysignf(r, x);
}

// f32x2 packed FFMA (sm_103a; only reachable via PTX)
#define FMA2(acc, a, b) asm("fma.rn.f32x2 %0, %1, %2, %0;" : "+l"(acc) : "l"(a), "l"(b))
#define PACKD(out, v)                                                        \
    do { unsigned _u = __float_as_uint(v);                                   \
         asm("mov.b64 %0, {%1, %1};" : "=l"(out) : "r"(_u)); } while (0)

__device__ __forceinline__ int ld_acq(const int* p) {
    int v; asm volatile("ld.acquire.gpu.global.b32 %0, [%1];" : "=r"(v) : "l"(p)); return v;
}
__device__ __forceinline__ void red_rel_add(int* p) {
    asm volatile("red.release.gpu.global.add.s32 [%0], %1;" :: "l"(p), "r"(1) : "memory");
}

// ------------------------------- init ---------------------------------------
__global__ void k_init() {
    if (threadIdx.x < 2) g_cnt[threadIdx.x] = 0;
}

// ------------------------- z / zp (tiny matvec) ------------------------------
__global__ void k_zzp(const float* __restrict__ hin, const float* __restrict__ W4,
                      const float* __restrict__ b4) {
    __shared__ float zs[D_];
    int b = blockIdx.x;
    int e = threadIdx.x;
    float s = 0.f;
#pragma unroll
    for (int a = 0; a < A_; ++a)
        s += hin[(((size_t)(a * B_ + b)) * S_ + (S_ - 1)) * D_ + e];
    zs[e] = s * (1.f / 3.f);
    __syncthreads();
    float acc = b4[e];
#pragma unroll 8
    for (int d = 0; d < D_; ++d) acc += zs[d] * W4[d * D_ + e];
    g_zp[b * D_ + e] = acc;
}

// ------------------------------ SGEMM ----------------------------------------
// C[M x NDIM] = op(A)[M x KDIM] @ Bw[KDIM x NDIM] + bias (+ optional zp + tanh)
// AMODE 0: A0[m][k]
// AMODE 1: A0[(n, S-1-s)][k]          (time-reversed rows; m = n*S+s)
// AMODE 3: concat from [t][n][j] layout:
//          k<256 -> A0[(s*32+n)][k] ; k>=256 -> A1[((S-1-s)*32+n)][k-256]
// EPI 0: +bias   EPI 1: tanh(v + bias + g_zp[b])
template <int AMODE, int EPI, int KDIM, int NDIM>
__global__ void __launch_bounds__(256, 2)
k_gemm(const float* __restrict__ A0, const float* __restrict__ A1,
       const float* __restrict__ Bw, const float* __restrict__ bias,
       float* __restrict__ C) {
    __shared__ float As[8][128];
    __shared__ float Bs[8][128];
    const int tid = threadIdx.x;
    const int m0 = blockIdx.y * 128;
    const int n0 = blockIdx.x * 128;
    const int aRow = tid >> 1;
    const int aCol = (tid & 1) * 4;
    const int bRow = tid >> 5;
    const int bCol = (tid & 31) * 4;
    const int tr = (tid >> 4) * 8;
    const int tc = (tid & 15) * 8;

    const int m = m0 + aRow;
    const float* aP0;
    const float* aP1 = nullptr;
    if (AMODE == 0) {
        aP0 = A0 + (size_t)m * KDIM;
    } else if (AMODE == 1) {
        int n = m >> 11, s = m & 2047;
        aP0 = A0 + ((size_t)(n << 11) + (2047 - s)) * KDIM;
    } else {
        int n = m >> 11, s = m & 2047;
        aP0 = A0 + ((size_t)(s * 32) + n) * 256;
        aP1 = A1 + ((size_t)((2047 - s) * 32) + n) * 256;
    }
    const float* bP = Bw + (size_t)bRow * NDIM + n0 + bCol;

    float acc[8][8];
#pragma unroll
    for (int i = 0; i < 8; ++i)
#pragma unroll
        for (int j = 0; j < 8; ++j) acc[i][j] = 0.f;

    for (int k0 = 0; k0 < KDIM; k0 += 8) {
        float4 av;
        if (AMODE != 3) {
            av = *(const float4*)(aP0 + k0 + aCol);
        } else {
            int kk = k0 + aCol;
            av = (kk < 256) ? *(const float4*)(aP0 + kk)
                            : *(const float4*)(aP1 + (kk - 256));
        }
        float4 bv = *(const float4*)(bP + (size_t)k0 * NDIM);
        As[aCol + 0][aRow] = av.x;
        As[aCol + 1][aRow] = av.y;
        As[aCol + 2][aRow] = av.z;
        As[aCol + 3][aRow] = av.w;
        *(float4*)&Bs[bRow][bCol] = bv;
        __syncthreads();
#pragma unroll
        for (int kk = 0; kk < 8; ++kk) {
            float ra[8], rb[8];
            *(float4*)(ra)     = *(const float4*)&As[kk][tr];
            *(float4*)(ra + 4) = *(const float4*)&As[kk][tr + 4];
            *(float4*)(rb)     = *(const float4*)&Bs[kk][tc];
            *(float4*)(rb + 4) = *(const float4*)&Bs[kk][tc + 4];
#pragma unroll
            for (int i = 0; i < 8; ++i)
#pragma unroll
                for (int j = 0; j < 8; ++j) acc[i][j] += ra[i] * rb[j];
        }
        __syncthreads();
    }

#pragma unroll
    for (int i = 0; i < 8; ++i) {
        int mm = m0 + tr + i;
        float* crow = C + (size_t)mm * NDIM + n0 + tc;
        int bi = 0;
        if (EPI == 1) bi = (mm >> 11) & 7;
#pragma unroll
        for (int j4 = 0; j4 < 8; j4 += 4) {
            int col = n0 + tc + j4;
            float4 v = make_float4(acc[i][j4], acc[i][j4 + 1], acc[i][j4 + 2], acc[i][j4 + 3]);
            v.x += bias[col]; v.y += bias[col + 1]; v.z += bias[col + 2]; v.w += bias[col + 3];
            if (EPI == 1) {
                const float* zr = &g_zp[bi * D_];
                v.x = ftanh(v.x + zr[col]);     v.y = ftanh(v.y + zr[col + 1]);
                v.z = ftanh(v.z + zr[col + 2]); v.w = ftanh(v.w + zr[col + 3]);
            }
            *(float4*)(crow + j4) = v;
        }
    }
}

// --------------------------- persistent LSTM scan ----------------------------
// 64 CTAs; CTA blk owns hidden units [blk*4, blk*4+4) for BOTH directions.
// Per step: fwd phase (gemm->reduce->activations->publish->arrive), then bwd
// phase. Each direction's barrier-propagation latency is hidden behind the
// other direction's compute. Sync: one monotonic counter per dir,
// red.release.gpu arrive + single-thread ld.acquire.gpu poll. No membar.
__global__ void __launch_bounds__(256, 1)
k_scan(const float* __restrict__ Whf, const float* __restrict__ Whb, int base) {
    __shared__ float Wsl[2][256 * WPAD];
    __shared__ float red[256 * WPAD];
    const int tid = threadIdx.x;
    const int lane = tid & 31;
    const int w = tid >> 5;
    const int blk = blockIdx.x;   // 0..63
    const int j0 = blk * JH;

    // Load both Wh slices: Wsl[d][k][jj*4+gt] = Wh_d[k][gt*256 + j0 + jj]
#pragma unroll
    for (int d = 0; d < 2; ++d) {
        const float* Wh = d ? Whb : Whf;
        const float* wr = Wh + (size_t)tid * G_ + j0;
        float4 q0 = *(const float4*)(wr);
        float4 q1 = *(const float4*)(wr + 256);
        float4 q2 = *(const float4*)(wr + 512);
        float4 q3 = *(const float4*)(wr + 768);
        float* ws = &Wsl[d][tid * WPAD];
        ws[0]  = q0.x; ws[1]  = q1.x; ws[2]  = q2.x; ws[3]  = q3.x;
        ws[4]  = q0.y; ws[5]  = q1.y; ws[6]  = q2.y; ws[7]  = q3.y;
        ws[8]  = q0.z; ws[9]  = q1.z; ws[10] = q2.z; ws[11] = q3.z;
        ws[12] = q0.w; ws[13] = q1.w; ws[14] = q2.w; ws[15] = q3.w;
    }
    __syncthreads();

    const int wk0 = w * 32;          // producer: K-chunk base, lane = seq
    const int n2 = tid >> 2;         // epilogue: seq (tid<128)
    const int jj = tid & 3;          //           hidden sub-index
    float creg[2] = {0.f, 0.f};

    for (int t = 0; t < S_; ++t) {
#pragma unroll
        for (int d = 0; d < 2; ++d) {
            const float* xw = d ? g_xw1 : g_xw0;
            float* hseq = d ? g_hseq1 : g_hseq0;

            // prefetch this phase's input projections (overlaps poll + GEMM)
            float xi = 0.f, xf = 0.f, xg = 0.f, xo = 0.f;
            if (tid < 128) {
                const float* xp = xw + ((size_t)n2 * S_ + t) * G_ + j0 + jj;
                xi = __ldcg(xp);
                xf = __ldcg(xp + 256);
                xg = __ldcg(xp + 512);
                xo = __ldcg(xp + 768);
            }

            ull acc2[8];
#pragma unroll
            for (int c = 0; c < 8; ++c) acc2[c] = 0ull;

            if (t > 0) {
                // wait for all CTAs to have published h_d[t-1] (likely already
                // satisfied: their arrival happened one phase ago)
                if (tid == 0) {
                    const int tgt = base + P_ * t;
                    while (ld_acq(&g_cnt[d]) < tgt) { }
                }
                __syncthreads();

                const float* hb = &g_hstate[d][(t + 1) & 1][wk0 * N_ + lane];
                float hreg[32];
#pragma unroll
                for (int kk = 0; kk < 32; ++kk) hreg[kk] = __ldcg(hb + kk * N_);
#pragma unroll
                for (int kk = 0; kk < 32; ++kk) {
                    const ulonglong2* wp = (const ulonglong2*)&Wsl[d][(wk0 + kk) * WPAD];
                    ulonglong2 wa = wp[0], wb = wp[1];
                    ull hp_; PACKD(hp_, hreg[kk]);
                    FMA2(acc2[0], wa.x, hp_); FMA2(acc2[1], wa.y, hp_);
                    FMA2(acc2[2], wb.x, hp_); FMA2(acc2[3], wb.y, hp_);
                    ulonglong2 wc = wp[2], wd = wp[3];
                    FMA2(acc2[4], wc.x, hp_); FMA2(acc2[5], wc.y, hp_);
                    FMA2(acc2[6], wd.x, hp_); FMA2(acc2[7], wd.y, hp_);
                }
            }

            {   // K-chunk partials -> smem
                ulonglong2* rr = (ulonglong2*)&red[tid * WPAD];
                rr[0] = make_ulonglong2(acc2[0], acc2[1]);
                rr[1] = make_ulonglong2(acc2[2], acc2[3]);
                rr[2] = make_ulonglong2(acc2[4], acc2[5]);
                rr[3] = make_ulonglong2(acc2[6], acc2[7]);
            }
            __syncthreads();

            if (tid < 128) {
                float4 s = make_float4(0.f, 0.f, 0.f, 0.f);
#pragma unroll
                for (int ww = 0; ww < 8; ++ww) {
                    float4 v = *(const float4*)&red[(ww * 32 + n2) * WPAD + jj * 4];
                    s.x += v.x; s.y += v.y; s.z += v.z; s.w += v.w;
                }
                float gi = s.x + xi, gf = s.y + xf, gg = s.z + xg, go = s.w + xo;
                float ii = fsig(gi), ff = fsig(gf);
                float g2 = ftanh(gg), oo = fsig(go);
                float c = ff * creg[d] + ii * g2;
                creg[d] = c;
                float hv = oo * ftanh(c);
                __stcg(&g_hstate[d][t & 1][(j0 + jj) * N_ + n2], hv);
                __stcg(&hseq[((size_t)t * N_ + n2) * H_ + j0 + jj], hv);
            }
            __syncthreads();   // all h stores done before the release below
            if (tid == 0) red_rel_add(&g_cnt[d]);
        }
    }
}

// ------------------------------ launcher -------------------------------------
extern "C" void kernel_launch(void* const* d_in, const int* in_sizes, int n_in,
                              void* d_out, int out_size) {
    const float* x   = (const float*)d_in[0];
    const float* W3  = (const float*)d_in[1];
    const float* b3  = (const float*)d_in[2];
    const float* W4  = (const float*)d_in[3];
    const float* b4  = (const float*)d_in[4];
    const float* Wxf = (const float*)d_in[5];
    const float* Whf = (const float*)d_in[6];
    const float* bf  = (const float*)d_in[7];
    const float* Wxb = (const float*)d_in[8];
    const float* Whb = (const float*)d_in[9];
    const float* bb  = (const float*)d_in[10];
    const float* Wd  = (const float*)d_in[11];
    const float* bd  = (const float*)d_in[12];
    float* out = (float*)d_out;

    float *pf, *pxw0, *pxw1, *ph0, *ph1, *phbuf;
    cudaGetSymbolAddress((void**)&pf,    g_f);
    cudaGetSymbolAddress((void**)&pxw0,  g_xw0);
    cudaGetSymbolAddress((void**)&pxw1,  g_xw1);
    cudaGetSymbolAddress((void**)&ph0,   g_hseq0);
    cudaGetSymbolAddress((void**)&ph1,   g_hseq1);
    cudaGetSymbolAddress((void**)&phbuf, g_hbuf);

    k_init<<<1, 32>>>();

    for (int it = 0; it < 2; ++it) {
        const float* hin = (it == 0) ? x : phbuf;
        float* hout = (it == 1) ? out : phbuf;

        // zp = (sum_a h[:, :, -1, :]/3) @ W4 + b4
        k_zzp<<<B_, D_>>>(hin, W4, b4);
        // f = tanh(h @ W3 + b3 + zp[b])
        k_gemm<0, 1, 256, 256><<<dim3(2, 512), 256>>>(hin, nullptr, W3, b3, pf);
        // gate input projections (fwd + time-reversed bwd)
        k_gemm<0, 0, 256, 1024><<<dim3(8, 512), 256>>>(pf, nullptr, Wxf, bf, pxw0);
        k_gemm<1, 0, 256, 1024><<<dim3(8, 512), 256>>>(pf, nullptr, Wxb, bb, pxw1);
        // persistent bidirectional LSTM scan (dir-interleaved latency hiding)
        k_scan<<<P_, 256>>>(Whf, Whb, it * P_ * S_);
        // h = concat(hf, hb_rev) @ Wd + bd   (hseq in [t][n][j] layout)
        k_gemm<3, 0, 512, 256><<<dim3(2, 512), 256>>>(ph0, ph1, Wd, bd, hout);
    }
}

// round 6
// speedup vs baseline: 1.7974x; 1.3865x over previous
#include <cuda_runtime.h>
#include <cstddef>
#include <cstdint>

typedef unsigned long long ull;

// Problem constants
#define A_ 4
#define B_ 8
#define S_ 2048
#define D_ 256
#define N_ 32      // A_*B_
#define H_ 256
#define G_ 1024    // 4*H_
#define CL 8       // cluster size (CTAs per sequence-group)

// -------- scratch (device globals; allocation-free per harness rules) --------
__device__ float g_f[(size_t)N_ * S_ * D_];
__device__ float g_xw0[(size_t)N_ * S_ * G_];
__device__ float g_xw1[(size_t)N_ * S_ * G_];
__device__ float g_hseq0[(size_t)S_ * N_ * H_];   // [t][n][j] layout
__device__ float g_hseq1[(size_t)S_ * N_ * H_];   // [t][n][j] layout
__device__ float g_hbuf[(size_t)N_ * S_ * D_];
__device__ float g_zp[B_ * D_];

__device__ __forceinline__ float fsig(float x) { return 1.f / (1.f + __expf(-x)); }
__device__ __forceinline__ float ftanh(float x) {
    float t = __expf(-2.f * fabsf(x));
    float r = (1.f - t) / (1.f + t);
    return copysignf(r, x);
}

// f32x2 packed FFMA (sm_103a; only reachable via PTX)
#define FMA2(acc, a, b) asm("fma.rn.f32x2 %0, %1, %2, %0;" : "+l"(acc) : "l"(a), "l"(b))
#define PACK2(out, lo, hi) \
    asm("mov.b64 %0, {%1, %2};" : "=l"(out) : "f"(lo), "f"(hi))
#define UNPK(lo, hi, v)                                                      \
    do { unsigned _a, _b;                                                    \
         asm("mov.b64 {%0, %1}, %2;" : "=r"(_a), "=r"(_b) : "l"(v));         \
         lo = __uint_as_float(_a); hi = __uint_as_float(_b); } while (0)

__device__ __forceinline__ unsigned ctarank() {
    unsigned r; asm("mov.u32 %0, %%cluster_ctarank;" : "=r"(r)); return r;
}
__device__ __forceinline__ unsigned smem_u32(const void* p) {
    return (unsigned)__cvta_generic_to_shared(p);
}
__device__ __forceinline__ unsigned mapa_u32(unsigned a, unsigned rank) {
    unsigned r;
    asm("mapa.shared::cluster.u32 %0, %1, %2;" : "=r"(r) : "r"(a), "r"(rank));
    return r;
}
__device__ __forceinline__ void st_cluster_f32(unsigned a, float v) {
    asm volatile("st.shared::cluster.f32 [%0], %1;" :: "r"(a), "f"(v) : "memory");
}
__device__ __forceinline__ void mbar_init(unsigned a, unsigned cnt) {
    asm volatile("mbarrier.init.shared.b64 [%0], %1;" :: "r"(a), "r"(cnt) : "memory");
}
__device__ __forceinline__ void mbar_arrive_cluster(unsigned a) {
    asm volatile("mbarrier.arrive.release.cluster.shared::cluster.b64 _, [%0];"
                 :: "r"(a) : "memory");
}
__device__ __forceinline__ void mbar_wait_cluster(unsigned a, unsigned parity) {
    asm volatile(
        "{\n\t.reg .pred P;\n\t"
        "W%=:\n\t"
        "mbarrier.try_wait.parity.acquire.cluster.shared::cta.b64 P, [%0], %1, 0x989680;\n\t"
        "@!P bra W%=;\n\t}"
        :: "r"(a), "r"(parity) : "memory");
}

// ------------------------- z / zp (tiny matvec) ------------------------------
__global__ void k_zzp(const float* __restrict__ hin, const float* __restrict__ W4,
                      const float* __restrict__ b4) {
    __shared__ float zs[D_];
    int b = blockIdx.x;
    int e = threadIdx.x;
    float s = 0.f;
#pragma unroll
    for (int a = 0; a < A_; ++a)
        s += hin[(((size_t)(a * B_ + b)) * S_ + (S_ - 1)) * D_ + e];
    zs[e] = s * (1.f / 3.f);
    __syncthreads();
    float acc = b4[e];
#pragma unroll 8
    for (int d = 0; d < D_; ++d) acc += zs[d] * W4[d * D_ + e];
    g_zp[b * D_ + e] = acc;
}

// ------------------------------ SGEMM ----------------------------------------
// C[M x NDIM] = op(A)[M x KDIM] @ Bw[KDIM x NDIM] + bias (+ optional zp + tanh)
// AMODE 0: A0[m][k]
// AMODE 1: A0[(n, S-1-s)][k]          (time-reversed rows; m = n*S+s)
// AMODE 3: concat from [t][n][j] layout:
//          k<256 -> A0[(s*32+n)][k] ; k>=256 -> A1[((S-1-s)*32+n)][k-256]
// EPI 0: +bias   EPI 1: tanh(v + bias + g_zp[b])
template <int AMODE, int EPI, int KDIM, int NDIM>
__global__ void __launch_bounds__(256, 2)
k_gemm(const float* __restrict__ A0, const float* __restrict__ A1,
       const float* __restrict__ Bw, const float* __restrict__ bias,
       float* __restrict__ C) {
    __shared__ float As[8][128];
    __shared__ float Bs[8][128];
    const int tid = threadIdx.x;
    const int m0 = blockIdx.y * 128;
    const int n0 = blockIdx.x * 128;
    const int aRow = tid >> 1;
    const int aCol = (tid & 1) * 4;
    const int bRow = tid >> 5;
    const int bCol = (tid & 31) * 4;
    const int tr = (tid >> 4) * 8;
    const int tc = (tid & 15) * 8;

    const int m = m0 + aRow;
    const float* aP0;
    const float* aP1 = nullptr;
    if (AMODE == 0) {
        aP0 = A0 + (size_t)m * KDIM;
    } else if (AMODE == 1) {
        int n = m >> 11, s = m & 2047;
        aP0 = A0 + ((size_t)(n << 11) + (2047 - s)) * KDIM;
    } else {
        int n = m >> 11, s = m & 2047;
        aP0 = A0 + ((size_t)(s * 32) + n) * 256;
        aP1 = A1 + ((size_t)((2047 - s) * 32) + n) * 256;
    }
    const float* bP = Bw + (size_t)bRow * NDIM + n0 + bCol;

    float acc[8][8];
#pragma unroll
    for (int i = 0; i < 8; ++i)
#pragma unroll
        for (int j = 0; j < 8; ++j) acc[i][j] = 0.f;

    for (int k0 = 0; k0 < KDIM; k0 += 8) {
        float4 av;
        if (AMODE != 3) {
            av = *(const float4*)(aP0 + k0 + aCol);
        } else {
            int kk = k0 + aCol;
            av = (kk < 256) ? *(const float4*)(aP0 + kk)
                            : *(const float4*)(aP1 + (kk - 256));
        }
        float4 bv = *(const float4*)(bP + (size_t)k0 * NDIM);
        As[aCol + 0][aRow] = av.x;
        As[aCol + 1][aRow] = av.y;
        As[aCol + 2][aRow] = av.z;
        As[aCol + 3][aRow] = av.w;
        *(float4*)&Bs[bRow][bCol] = bv;
        __syncthreads();
#pragma unroll
        for (int kk = 0; kk < 8; ++kk) {
            float ra[8], rb[8];
            *(float4*)(ra)     = *(const float4*)&As[kk][tr];
            *(float4*)(ra + 4) = *(const float4*)&As[kk][tr + 4];
            *(float4*)(rb)     = *(const float4*)&Bs[kk][tc];
            *(float4*)(rb + 4) = *(const float4*)&Bs[kk][tc + 4];
#pragma unroll
            for (int i = 0; i < 8; ++i)
#pragma unroll
                for (int j = 0; j < 8; ++j) acc[i][j] += ra[i] * rb[j];
        }
        __syncthreads();
    }

#pragma unroll
    for (int i = 0; i < 8; ++i) {
        int mm = m0 + tr + i;
        float* crow = C + (size_t)mm * NDIM + n0 + tc;
        int bi = 0;
        if (EPI == 1) bi = (mm >> 11) & 7;
#pragma unroll
        for (int j4 = 0; j4 < 8; j4 += 4) {
            int col = n0 + tc + j4;
            float4 v = make_float4(acc[i][j4], acc[i][j4 + 1], acc[i][j4 + 2], acc[i][j4 + 3]);
            v.x += bias[col]; v.y += bias[col + 1]; v.z += bias[col + 2]; v.w += bias[col + 3];
            if (EPI == 1) {
                const float* zr = &g_zp[bi * D_];
                v.x = ftanh(v.x + zr[col]);     v.y = ftanh(v.y + zr[col + 1]);
                v.z = ftanh(v.z + zr[col + 2]); v.w = ftanh(v.w + zr[col + 3]);
            }
            *(float4*)(crow + j4) = v;
        }
    }
}

// --------------------------- cluster LSTM scan -------------------------------
// 16 clusters x 8 CTAs. Cluster c: dir = c>>3, seq group sg = c&7 (4 seqs).
// CTA rank r owns hidden units [32r, 32r+32) for those 4 seqs.
// Wh slice (256K x 32units x 4gates) lives in REGISTERS as k-pair f32x2 (64
// ull/thread). Per step: FFMA2 gate GEMM reading h from local smem (broadcast
// LDS.128) -> smem reduction over K-halves -> activations -> h pushed to all 8
// CTAs' smem via pre-mapa'd st.shared::cluster -> mbarrier arrive (release
// .cluster) on every CTA; consumers try_wait (acquire.cluster). Parity ring of
// 2 mbarriers. No gpu-scope sync anywhere in the loop.
__global__ void __launch_bounds__(256, 1) __cluster_dims__(CL, 1, 1)
k_scan(const float* __restrict__ Whf, const float* __restrict__ Whb) {
    __shared__ __align__(16) float hbuf[2][4][256];     // [buf][s][k]  8KB
    __shared__ __align__(16) ull red[2][4][4][32];      // [kh][gate][s][u] 8KB
    __shared__ __align__(8)  ull mbar[2];

    const int tid = threadIdx.x;
    const unsigned rank = ctarank();
    const int cid = blockIdx.x >> 3;
    const int dir = cid >> 3;
    const int sg  = cid & 7;
    const float* Wh   = dir ? Whb : Whf;
    const float* xw   = dir ? g_xw1 : g_xw0;
    float*       hseq = dir ? g_hseq1 : g_hseq0;
    const int ju0 = (int)rank * 32;

    if (tid == 0) {
        mbar_init(smem_u32(&mbar[0]), CL);
        mbar_init(smem_u32(&mbar[1]), CL);
    }

    // ---- load Wh slice into registers (k-pair packed f32x2) ----
    const int kh   = tid >> 7;        // K half (0..1)
    const int c    = tid & 127;       // gate*32 + unit
    const int gate = c >> 5;
    const int u    = c & 31;
    const int gcol = gate * 256 + ju0 + u;
    ull W2[64];
#pragma unroll
    for (int k2 = 0; k2 < 64; ++k2) {
        const int k = kh * 128 + 2 * k2;
        float lo = __ldg(Wh + (size_t)k * G_ + gcol);
        float hi = __ldg(Wh + (size_t)(k + 1) * G_ + gcol);
        PACK2(W2[k2], lo, hi);
    }
    __syncthreads();
    // all mbarriers must be initialized cluster-wide before first arrive
    asm volatile("barrier.cluster.arrive.aligned;" ::: "memory");
    asm volatile("barrier.cluster.wait.aligned;" ::: "memory");

    // ---- precompute DSMEM push / arrive addresses ----
    const int es = tid >> 5;          // epilogue: seq (tid<128)
    const int ue = tid & 31;          //           unit
    unsigned pa[CL];
    if (tid < 128) {
        unsigned la = smem_u32(&hbuf[0][es][ju0 + ue]);
#pragma unroll
        for (unsigned r = 0; r < CL; ++r) pa[r] = mapa_u32(la, r);
    }
    unsigned am0 = 0, am1 = 0;
    if (tid < CL) {
        am0 = mapa_u32(smem_u32(&mbar[0]), (unsigned)tid);
        am1 = am0 + 8;
    }
    const int nG = sg * 4 + es;       // global sequence (tid<128)
    float creg = 0.f;

    for (int t = 0; t < S_; ++t) {
        const int buf = t & 1;

        // prefetch this step's input projections (overlaps wait + GEMM)
        float xi = 0.f, xf = 0.f, xg = 0.f, xo = 0.f;
        if (tid < 128) {
            const float* xp = xw + ((size_t)nG * S_ + t) * G_ + ju0 + ue;
            xi = __ldcg(xp);
            xf = __ldcg(xp + 256);
            xg = __ldcg(xp + 512);
            xo = __ldcg(xp + 768);
        }

        ull acc[4] = {0ull, 0ull, 0ull, 0ull};
        if (t > 0) {
            mbar_wait_cluster(smem_u32(&mbar[(t - 1) & 1]), ((t - 1) >> 1) & 1);
            const float* hb = &hbuf[buf ^ 1][0][kh * 128];
#pragma unroll
            for (int q = 0; q < 16; ++q) {
#pragma unroll
                for (int s = 0; s < 4; ++s) {
                    ulonglong2 h01 = *(const ulonglong2*)(hb + s * 256 + q * 8);
                    ulonglong2 h23 = *(const ulonglong2*)(hb + s * 256 + q * 8 + 4);
                    FMA2(acc[s], W2[q * 4 + 0], h01.x);
                    FMA2(acc[s], W2[q * 4 + 1], h01.y);
                    FMA2(acc[s], W2[q * 4 + 2], h23.x);
                    FMA2(acc[s], W2[q * 4 + 3], h23.y);
                }
            }
        }
        red[kh][gate][0][u] = acc[0];
        red[kh][gate][1][u] = acc[1];
        red[kh][gate][2][u] = acc[2];
        red[kh][gate][3][u] = acc[3];
        __syncthreads();

        if (tid < 128) {
            float v[4];
#pragma unroll
            for (int g = 0; g < 4; ++g) {
                float a, b, cc, d;
                UNPK(a, b, red[0][g][es][ue]);
                UNPK(cc, d, red[1][g][es][ue]);
                v[g] = (a + b) + (cc + d);
            }
            float gi = v[0] + xi, gf = v[1] + xf, gg = v[2] + xg, go = v[3] + xo;
            float ii = fsig(gi), ff = fsig(gf);
            float g2 = ftanh(gg), oo = fsig(go);
            creg = ff * creg + ii * g2;
            float hv = oo * ftanh(creg);
            __stcg(&hseq[((size_t)t * N_ + nG) * H_ + ju0 + ue], hv);
            if (t < S_ - 1) {
                const unsigned boff = (unsigned)buf << 12;   // buf*4096 bytes
#pragma unroll
                for (int r = 0; r < CL; ++r) st_cluster_f32(pa[r] + boff, hv);
            }
        }
        __syncthreads();   // all pushes ordered before the release-arrive
        if (t < S_ - 1 && tid < CL)
            mbar_arrive_cluster(buf ? am1 : am0);
    }

    if (tid == 0) {
        asm volatile("mbarrier.inval.shared.b64 [%0];" :: "r"(smem_u32(&mbar[0])) : "memory");
        asm volatile("mbarrier.inval.shared.b64 [%0];" :: "r"(smem_u32(&mbar[1])) : "memory");
    }
    asm volatile("barrier.cluster.arrive.aligned;" ::: "memory");
    asm volatile("barrier.cluster.wait.aligned;" ::: "memory");
}

// ------------------------------ launcher -------------------------------------
extern "C" void kernel_launch(void* const* d_in, const int* in_sizes, int n_in,
                              void* d_out, int out_size) {
    const float* x   = (const float*)d_in[0];
    const float* W3  = (const float*)d_in[1];
    const float* b3  = (const float*)d_in[2];
    const float* W4  = (const float*)d_in[3];
    const float* b4  = (const float*)d_in[4];
    const float* Wxf = (const float*)d_in[5];
    const float* Whf = (const float*)d_in[6];
    const float* bf  = (const float*)d_in[7];
    const float* Wxb = (const float*)d_in[8];
    const float* Whb = (const float*)d_in[9];
    const float* bb  = (const float*)d_in[10];
    const float* Wd  = (const float*)d_in[11];
    const float* bd  = (const float*)d_in[12];
    float* out = (float*)d_out;

    float *pf, *pxw0, *pxw1, *ph0, *ph1, *phbuf;
    cudaGetSymbolAddress((void**)&pf,    g_f);
    cudaGetSymbolAddress((void**)&pxw0,  g_xw0);
    cudaGetSymbolAddress((void**)&pxw1,  g_xw1);
    cudaGetSymbolAddress((void**)&ph0,   g_hseq0);
    cudaGetSymbolAddress((void**)&ph1,   g_hseq1);
    cudaGetSymbolAddress((void**)&phbuf, g_hbuf);

    for (int it = 0; it < 2; ++it) {
        const float* hin = (it == 0) ? x : phbuf;
        float* hout = (it == 1) ? out : phbuf;

        // zp = (sum_a h[:, :, -1, :]/3) @ W4 + b4
        k_zzp<<<B_, D_>>>(hin, W4, b4);
        // f = tanh(h @ W3 + b3 + zp[b])
        k_gemm<0, 1, 256, 256><<<dim3(2, 512), 256>>>(hin, nullptr, W3, b3, pf);
        // gate input projections (fwd + time-reversed bwd)
        k_gemm<0, 0, 256, 1024><<<dim3(8, 512), 256>>>(pf, nullptr, Wxf, bf, pxw0);
        k_gemm<1, 0, 256, 1024><<<dim3(8, 512), 256>>>(pf, nullptr, Wxb, bb, pxw1);
        // cluster-local bidirectional LSTM scan (mbarrier + DSMEM push)
        k_scan<<<16 * CL, 256>>>(Whf, Whb);
        // h = concat(hf, hb_rev) @ Wd + bd   (hseq in [t][n][j] layout)
        k_gemm<3, 0, 512, 256><<<dim3(2, 512), 256>>>(ph0, ph1, Wd, bd, hout);
    }
}